// round 1
// baseline (speedup 1.0000x reference)
#include <cuda_runtime.h>
#include <math.h>
#include <limits.h>

// Problem constants
#define L_LAYERS 32
#define BEAM 8
#define KV2 2
#define HEADS 8
#define SEQ 1024
#define HDIM 64
#define VOCAB 50257
#define HIST 128
#define TOPK 8

// Derived
#define CH  (KV2*HEADS*SEQ*HDIM)        // floats per (layer, beam) chunk = 1,048,576
#define CH4 (CH/4)                      // float4 per chunk = 262,144
#define TOTAL4 (L_LAYERS*BEAM*CH4)      // 67,108,864 float4

// Output layout (flattened tuple, all as float32):
// [0 .. 268435456)                 kv_gathered
// [OFF_SAVE .. +8*129)             new_save_id (ints as float)
// [OFF_PROB .. +8)                 top_beam_prob
// [OFF_TBI  .. +8)                 tbi (ints as float)
// [OFF_MAX  .. +1)                 max_logits_idx
#define OFF_SAVE 268435456
#define OFF_PROB (OFF_SAVE + BEAM*(HIST+1))
#define OFF_TBI  (OFF_PROB + BEAM)
#define OFF_MAX  (OFF_TBI + BEAM)

// Device scratch (no allocations allowed)
__device__ float g_lse[BEAM];
__device__ float g_topk_val[BEAM][TOPK];
__device__ int   g_topk_idx[BEAM][TOPK];
__device__ int   g_beam_index[BEAM];

// ---------------------------------------------------------------------------
// Kernel 1: per-beam logsumexp + top-8 (value desc, tie -> lower index)
// grid = BEAM blocks, 1024 threads
// ---------------------------------------------------------------------------
__global__ void __launch_bounds__(1024) topk_lse_kernel(const float* __restrict__ logits)
{
    const int b = blockIdx.x;
    const int tid = threadIdx.x;
    const float* row = logits + (long long)b * VOCAB;

    __shared__ float sval[1024];
    __shared__ float ssum[1024];
    __shared__ int   sidx[1024];
    __shared__ int   stid[1024];

    // Thread-local: online (m, s) for LSE + sorted top-8 list
    float lv[TOPK];
    int   li[TOPK];
#pragma unroll
    for (int i = 0; i < TOPK; i++) { lv[i] = -INFINITY; li[i] = INT_MAX; }

    float m = -INFINITY, s = 0.0f;
    for (int j = tid; j < VOCAB; j += 1024) {
        float v = row[j];
        // online logsumexp
        if (v > m) {
            s = s * expf(m - v) + 1.0f;
            m = v;
        } else {
            s += expf(v - m);
        }
        // top-8 insertion (strict >, so earlier index wins ties)
        if (v > lv[TOPK - 1]) {
            int p = TOPK - 1;
#pragma unroll
            for (int q = TOPK - 1; q > 0; q--) {
                if (v > lv[q - 1]) {
                    lv[q] = lv[q - 1]; li[q] = li[q - 1];
                    p = q - 1;
                }
            }
            lv[p] = v; li[p] = j;
        }
    }

    // Block-reduce (m, s)
    sval[tid] = m; ssum[tid] = s;
    __syncthreads();
    for (int off = 512; off > 0; off >>= 1) {
        if (tid < off) {
            float m2 = sval[tid + off], s2 = ssum[tid + off];
            float m1 = sval[tid],       s1 = ssum[tid];
            float nm = fmaxf(m1, m2);
            ssum[tid] = s1 * expf(m1 - nm) + s2 * expf(m2 - nm);
            sval[tid] = nm;
        }
        __syncthreads();
    }
    if (tid == 0) g_lse[b] = sval[0] + logf(ssum[0]);
    __syncthreads();

    // 8 rounds of block-argmax over each thread's current list head.
    int p = 0;
    for (int r = 0; r < TOPK; r++) {
        bool valid = (p < TOPK);
        sval[tid] = valid ? lv[p] : -INFINITY;
        sidx[tid] = valid ? li[p] : INT_MAX;
        stid[tid] = tid;
        __syncthreads();
        for (int off = 512; off > 0; off >>= 1) {
            if (tid < off) {
                float v2 = sval[tid + off];
                int   i2 = sidx[tid + off];
                float v1 = sval[tid];
                int   i1 = sidx[tid];
                if (v2 > v1 || (v2 == v1 && i2 < i1)) {
                    sval[tid] = v2; sidx[tid] = i2; stid[tid] = stid[tid + off];
                }
            }
            __syncthreads();
        }
        if (tid == 0) {
            g_topk_val[b][r] = sval[0];
            g_topk_idx[b][r] = sidx[0];
        }
        int winner = stid[0];
        __syncthreads();           // everyone read winner before shared reuse
        if (tid == winner) p++;
    }
}

// ---------------------------------------------------------------------------
// Kernel 2: combine 64 candidates, top-8 beams, write small outputs
// 1 block, 256 threads
// ---------------------------------------------------------------------------
__global__ void __launch_bounds__(256) select_kernel(const float* __restrict__ prev_prob,
                                                     const int*   __restrict__ save_id,
                                                     float*       __restrict__ out)
{
    __shared__ int s_beam[BEAM];
    __shared__ int s_tbi[BEAM];

    if (threadIdx.x == 0) {
        float cand[BEAM * TOPK];
#pragma unroll
        for (int b = 0; b < BEAM; b++) {
            float lse = g_lse[b];
            float pp  = prev_prob[b];
#pragma unroll
            for (int j = 0; j < TOPK; j++)
                cand[b * TOPK + j] = g_topk_val[b][j] - lse + pp;
        }
        bool used[BEAM * TOPK];
#pragma unroll
        for (int c = 0; c < BEAM * TOPK; c++) used[c] = false;

        for (int r = 0; r < BEAM; r++) {
            int best = -1; float bv = -INFINITY;
            for (int c = 0; c < BEAM * TOPK; c++) {
                if (!used[c] && cand[c] > bv) { bv = cand[c]; best = c; }  // ties -> lower flat idx
            }
            used[best] = true;
            int bi = best >> 3;            // best / top_k
            int ti = g_topk_idx[bi][best & 7];
            s_beam[r] = bi;
            s_tbi[r]  = ti;
            g_beam_index[r] = bi;
            out[OFF_PROB + r] = bv;
            out[OFF_TBI + r]  = (float)ti;
        }
        out[OFF_MAX] = (float)s_tbi[0];
    }
    __syncthreads();

    // new_save_id[b][0:128] = save_id[beam_index[b]]; [128] = tbi[b]
    for (int e = threadIdx.x; e < BEAM * (HIST + 1); e += blockDim.x) {
        int bn = e / (HIST + 1);
        int c  = e - bn * (HIST + 1);
        float v = (c < HIST) ? (float)save_id[s_beam[bn] * HIST + c]
                             : (float)s_tbi[bn];
        out[OFF_SAVE + e] = v;
    }
}

// ---------------------------------------------------------------------------
// Kernel 3: 1 GiB beam-permuted gather of kv_cache, float4, coalesced.
// grid = 4096 x 256 -> 1,048,576 threads, exactly 64 iterations each.
// ---------------------------------------------------------------------------
__global__ void __launch_bounds__(256) gather_kernel(const float4* __restrict__ kv,
                                                     float4*       __restrict__ out)
{
    unsigned int tid    = blockIdx.x * 256u + threadIdx.x;
    const unsigned int stride = 4096u * 256u;          // 1,048,576

    // beam map to registers (8 loads, L1-resident afterwards)
    int bm[BEAM];
#pragma unroll
    for (int i = 0; i < BEAM; i++) bm[i] = g_beam_index[i];

#pragma unroll 4
    for (int it = 0; it < TOTAL4 / (4096 * 256); it++) {   // 64 iters
        unsigned int idx   = tid + (unsigned int)it * stride;
        unsigned int lb    = idx >> 18;                    // idx / CH4
        unsigned int inner = idx & (CH4 - 1u);
        unsigned int b     = lb & 7u;
        unsigned int l     = lb >> 3;
        unsigned int src   = ((l << 3) + (unsigned int)bm[b]) * (unsigned int)CH4 + inner;
        out[idx] = kv[src];
    }
}

// ---------------------------------------------------------------------------
extern "C" void kernel_launch(void* const* d_in, const int* in_sizes, int n_in,
                              void* d_out, int out_size)
{
    const float* kv_cache  = (const float*)d_in[0];
    const float* logits    = (const float*)d_in[1];
    const int*   save_id   = (const int*)d_in[2];
    const float* prev_prob = (const float*)d_in[3];
    float* out = (float*)d_out;

    topk_lse_kernel<<<BEAM, 1024>>>(logits);
    select_kernel<<<1, 256>>>(prev_prob, save_id, out);
    gather_kernel<<<4096, 256>>>((const float4*)kv_cache, (float4*)out);
}

// round 2
// speedup vs baseline: 1.0837x; 1.0837x over previous
#include <cuda_runtime.h>
#include <math.h>
#include <limits.h>

// Problem constants
#define L_LAYERS 32
#define BEAM 8
#define KV2 2
#define HEADS 8
#define SEQ 1024
#define HDIM 64
#define VOCAB 50257
#define HIST 128
#define TOPK 8
#define PARTS 32
#define SEG ((VOCAB + PARTS - 1) / PARTS)   // 1571

// Derived
#define CH  (KV2*HEADS*SEQ*HDIM)        // floats per (layer, beam) chunk = 1,048,576
#define CH4 (CH/4)                      // float4 per chunk = 262,144
#define TOTAL4 (L_LAYERS*BEAM*CH4)      // 67,108,864 float4

// Output layout (flattened tuple, all as float32)
#define OFF_SAVE 268435456
#define OFF_PROB (OFF_SAVE + BEAM*(HIST+1))
#define OFF_TBI  (OFF_PROB + BEAM)
#define OFF_MAX  (OFF_TBI + BEAM)

// Device scratch (no allocations allowed)
__device__ float g_pm[BEAM][PARTS];
__device__ float g_ps[BEAM][PARTS];
__device__ float g_pval[BEAM][PARTS][TOPK];
__device__ int   g_pidx[BEAM][PARTS][TOPK];
__device__ float g_lse[BEAM];
__device__ float g_topk_val[BEAM][TOPK];
__device__ int   g_topk_idx[BEAM][TOPK];
__device__ int   g_beam_index[BEAM];

// ---------------------------------------------------------------------------
// Phase A: per-(beam,segment) online logsumexp partials + segment top-8.
// grid = BEAM*PARTS = 256 blocks, 256 threads.
// ---------------------------------------------------------------------------
__global__ void __launch_bounds__(256) partial_kernel(const float* __restrict__ logits)
{
    const int blk  = blockIdx.x;
    const int beam = blk >> 5;        // / PARTS
    const int part = blk & 31;        // % PARTS
    const int tid  = threadIdx.x;
    const float* row = logits + beam * VOCAB;

    const int start = part * SEG;
    const int end   = min(start + SEG, VOCAB);

    __shared__ float sval[256];
    __shared__ float ssum[256];
    __shared__ int   sidx[256];
    __shared__ int   stid[256];

    // thread-local online (m,s) + sorted top-8 (≤7 real entries)
    float lv[TOPK];
    int   li[TOPK];
#pragma unroll
    for (int i = 0; i < TOPK; i++) { lv[i] = -INFINITY; li[i] = INT_MAX; }

    float m = -INFINITY, s = 0.0f;
    for (int j = start + tid; j < end; j += 256) {
        float v = row[j];
        if (v > m) { s = s * expf(m - v) + 1.0f; m = v; }
        else       { s += expf(v - m); }
        if (v > lv[TOPK - 1]) {
            int p = TOPK - 1;
#pragma unroll
            for (int q = TOPK - 1; q > 0; q--) {
                if (v > lv[q - 1]) { lv[q] = lv[q - 1]; li[q] = li[q - 1]; p = q - 1; }
            }
            lv[p] = v; li[p] = j;
        }
    }

    // block reduce (m, s)
    sval[tid] = m; ssum[tid] = s;
    __syncthreads();
    for (int off = 128; off > 0; off >>= 1) {
        if (tid < off) {
            float m2 = sval[tid + off], s2 = ssum[tid + off];
            float m1 = sval[tid],       s1 = ssum[tid];
            float nm = fmaxf(m1, m2);
            ssum[tid] = s1 * expf(m1 - nm) + s2 * expf(m2 - nm);
            sval[tid] = nm;
        }
        __syncthreads();
    }
    if (tid == 0) { g_pm[beam][part] = sval[0]; g_ps[beam][part] = ssum[0]; }
    __syncthreads();

    // 8 rounds of block argmax over each thread's sorted-list head
    int p = 0;
    for (int r = 0; r < TOPK; r++) {
        bool valid = (p < TOPK);
        sval[tid] = valid ? lv[p] : -INFINITY;
        sidx[tid] = valid ? li[p] : INT_MAX;
        stid[tid] = tid;
        __syncthreads();
        for (int off = 128; off > 0; off >>= 1) {
            if (tid < off) {
                float v2 = sval[tid + off]; int i2 = sidx[tid + off];
                float v1 = sval[tid];       int i1 = sidx[tid];
                if (v2 > v1 || (v2 == v1 && i2 < i1)) {
                    sval[tid] = v2; sidx[tid] = i2; stid[tid] = stid[tid + off];
                }
            }
            __syncthreads();
        }
        if (tid == 0) {
            g_pval[beam][part][r] = sval[0];
            g_pidx[beam][part][r] = sidx[0];
        }
        int winner = stid[0];
        __syncthreads();
        if (tid == winner) p++;
    }
}

// ---------------------------------------------------------------------------
// Phase B: merge 32 partials per beam -> lse + top-8.
// grid = BEAM blocks, 256 threads (one candidate per thread).
// ---------------------------------------------------------------------------
__global__ void __launch_bounds__(256) merge_kernel()
{
    const int b   = blockIdx.x;
    const int tid = threadIdx.x;

    __shared__ float sval[256];
    __shared__ int   sidx[256];
    __shared__ int   stid[256];

    if (tid == 0) {
        float nm = -INFINITY;
#pragma unroll
        for (int i = 0; i < PARTS; i++) nm = fmaxf(nm, g_pm[b][i]);
        float s = 0.0f;
#pragma unroll
        for (int i = 0; i < PARTS; i++) s += g_ps[b][i] * expf(g_pm[b][i] - nm);
        g_lse[b] = nm + logf(s);
    }

    // one candidate per thread: (part = tid>>3, slot = tid&7)
    float v  = g_pval[b][tid >> 3][tid & 7];
    int   id = g_pidx[b][tid >> 3][tid & 7];

    for (int r = 0; r < TOPK; r++) {
        sval[tid] = v; sidx[tid] = id; stid[tid] = tid;
        __syncthreads();
        for (int off = 128; off > 0; off >>= 1) {
            if (tid < off) {
                float v2 = sval[tid + off]; int i2 = sidx[tid + off];
                float v1 = sval[tid];       int i1 = sidx[tid];
                if (v2 > v1 || (v2 == v1 && i2 < i1)) {
                    sval[tid] = v2; sidx[tid] = i2; stid[tid] = stid[tid + off];
                }
            }
            __syncthreads();
        }
        if (tid == 0) {
            g_topk_val[b][r] = sval[0];
            g_topk_idx[b][r] = sidx[0];
        }
        int winner = stid[0];
        __syncthreads();
        if (tid == winner) v = -INFINITY;   // pop
    }
}

// ---------------------------------------------------------------------------
// Kernel 3: combine 64 candidates, top-8 beams, write small outputs
// ---------------------------------------------------------------------------
__global__ void __launch_bounds__(256) select_kernel(const float* __restrict__ prev_prob,
                                                     const int*   __restrict__ save_id,
                                                     float*       __restrict__ out)
{
    __shared__ int s_beam[BEAM];
    __shared__ int s_tbi[BEAM];

    if (threadIdx.x == 0) {
        float cand[BEAM * TOPK];
#pragma unroll
        for (int b = 0; b < BEAM; b++) {
            float lse = g_lse[b];
            float pp  = prev_prob[b];
#pragma unroll
            for (int j = 0; j < TOPK; j++)
                cand[b * TOPK + j] = g_topk_val[b][j] - lse + pp;
        }
        bool used[BEAM * TOPK];
#pragma unroll
        for (int c = 0; c < BEAM * TOPK; c++) used[c] = false;

        for (int r = 0; r < BEAM; r++) {
            int best = -1; float bv = -INFINITY;
            for (int c = 0; c < BEAM * TOPK; c++) {
                if (!used[c] && cand[c] > bv) { bv = cand[c]; best = c; }
            }
            used[best] = true;
            int bi = best >> 3;
            int ti = g_topk_idx[bi][best & 7];
            s_beam[r] = bi;
            s_tbi[r]  = ti;
            g_beam_index[r] = bi;
            out[OFF_PROB + r] = bv;
            out[OFF_TBI + r]  = (float)ti;
        }
        out[OFF_MAX] = (float)s_tbi[0];
    }
    __syncthreads();

    for (int e = threadIdx.x; e < BEAM * (HIST + 1); e += blockDim.x) {
        int bn = e / (HIST + 1);
        int c  = e - bn * (HIST + 1);
        float v = (c < HIST) ? (float)save_id[s_beam[bn] * HIST + c]
                             : (float)s_tbi[bn];
        out[OFF_SAVE + e] = v;
    }
}

// ---------------------------------------------------------------------------
// Kernel 4: 1 GiB beam-permuted gather, float4, coalesced.
// ---------------------------------------------------------------------------
__global__ void __launch_bounds__(256) gather_kernel(const float4* __restrict__ kv,
                                                     float4*       __restrict__ out)
{
    unsigned int tid = blockIdx.x * 256u + threadIdx.x;
    const unsigned int stride = 4096u * 256u;   // 1,048,576

    int bm[BEAM];
#pragma unroll
    for (int i = 0; i < BEAM; i++) bm[i] = g_beam_index[i];

#pragma unroll 8
    for (int it = 0; it < TOTAL4 / (4096 * 256); it++) {   // 64 iters
        unsigned int idx   = tid + (unsigned int)it * stride;
        unsigned int lb    = idx >> 18;                    // idx / CH4
        unsigned int inner = idx & (CH4 - 1u);
        unsigned int b     = lb & 7u;
        unsigned int l     = lb >> 3;
        unsigned int src   = ((l << 3) + (unsigned int)bm[b]) * (unsigned int)CH4 + inner;
        out[idx] = kv[src];
    }
}

// ---------------------------------------------------------------------------
extern "C" void kernel_launch(void* const* d_in, const int* in_sizes, int n_in,
                              void* d_out, int out_size)
{
    const float* kv_cache  = (const float*)d_in[0];
    const float* logits    = (const float*)d_in[1];
    const int*   save_id   = (const int*)d_in[2];
    const float* prev_prob = (const float*)d_in[3];
    float* out = (float*)d_out;

    partial_kernel<<<BEAM * PARTS, 256>>>(logits);
    merge_kernel<<<BEAM, 256>>>();
    select_kernel<<<1, 256>>>(prev_prob, save_id, out);
    gather_kernel<<<4096, 256>>>((const float4*)kv_cache, (float4*)out);
}

// round 5
// speedup vs baseline: 1.1032x; 1.0180x over previous
#include <cuda_runtime.h>
#include <math.h>
#include <limits.h>

// Problem constants
#define L_LAYERS 32
#define BEAM 8
#define KV2 2
#define HEADS 8
#define SEQ 1024
#define HDIM 64
#define VOCAB 50257
#define HIST 128
#define TOPK 8
#define PARTS 32
#define SEG ((VOCAB + PARTS - 1) / PARTS)   // 1571

// Derived
#define CH  (KV2*HEADS*SEQ*HDIM)        // floats per (layer, beam) chunk = 1,048,576
#define CH4 (CH/4)                      // float4 per chunk = 262,144
#define TOTAL4 (L_LAYERS*BEAM*CH4)      // 67,108,864 float4

// Output layout (flattened tuple, all as float32)
#define OFF_SAVE 268435456
#define OFF_PROB (OFF_SAVE + BEAM*(HIST+1))
#define OFF_TBI  (OFF_PROB + BEAM)
#define OFF_MAX  (OFF_TBI + BEAM)

// Device scratch (no allocations allowed)
__device__ float g_pm[BEAM][PARTS];
__device__ float g_ps[BEAM][PARTS];
__device__ float g_pval[BEAM][PARTS][TOPK];
__device__ int   g_pidx[BEAM][PARTS][TOPK];
__device__ unsigned int g_counter = 0;
__device__ unsigned long long g_beam_packed;   // 8 bits per beam

// ordered-float mapping: monotonic float -> uint32
__device__ __forceinline__ unsigned int ford(float v) {
    unsigned int u = __float_as_uint(v);
    return (u & 0x80000000u) ? ~u : (u | 0x80000000u);
}
__device__ __forceinline__ float funord(unsigned int u) {
    u = (u & 0x80000000u) ? (u & 0x7FFFFFFFu) : ~u;
    return __uint_as_float(u);
}

// ---------------------------------------------------------------------------
// Fused kernel: per-(beam,part) partials; last block merges + selects.
// grid = BEAM*PARTS = 256 blocks, 256 threads.
// ---------------------------------------------------------------------------
__global__ void __launch_bounds__(256) selection_kernel(const float* __restrict__ logits,
                                                        const float* __restrict__ prev_prob,
                                                        const int*   __restrict__ save_id,
                                                        float*       __restrict__ out)
{
    const int blk  = blockIdx.x;
    const int beam = blk >> 5;        // / PARTS
    const int part = blk & 31;        // % PARTS
    const int tid  = threadIdx.x;
    const float* row = logits + beam * VOCAB;

    const int start = part * SEG;
    const int end   = min(start + SEG, VOCAB);

    __shared__ float sval[256];
    __shared__ float ssum[256];
    __shared__ int   sidx[256];
    __shared__ int   stid[256];
    __shared__ int   s_last;

    // ---------------- Phase A: partials ----------------
    float lv[TOPK];
    int   li[TOPK];
#pragma unroll
    for (int i = 0; i < TOPK; i++) { lv[i] = -INFINITY; li[i] = INT_MAX; }

    float m = -INFINITY, s = 0.0f;
    for (int j = start + tid; j < end; j += 256) {
        float v = row[j];
        if (v > m) { s = s * expf(m - v) + 1.0f; m = v; }
        else       { s += expf(v - m); }
        if (v > lv[TOPK - 1]) {
            int p = TOPK - 1;
#pragma unroll
            for (int q = TOPK - 1; q > 0; q--) {
                if (v > lv[q - 1]) { lv[q] = lv[q - 1]; li[q] = li[q - 1]; p = q - 1; }
            }
            lv[p] = v; li[p] = j;
        }
    }

    // block reduce (m, s)
    sval[tid] = m; ssum[tid] = s;
    __syncthreads();
    for (int off = 128; off > 0; off >>= 1) {
        if (tid < off) {
            float m2 = sval[tid + off], s2 = ssum[tid + off];
            float m1 = sval[tid],       s1 = ssum[tid];
            float nm = fmaxf(m1, m2);
            ssum[tid] = s1 * expf(m1 - nm) + s2 * expf(m2 - nm);
            sval[tid] = nm;
        }
        __syncthreads();
    }
    if (tid == 0) { g_pm[beam][part] = sval[0]; g_ps[beam][part] = ssum[0]; }
    __syncthreads();

    // 8 rounds of block argmax
    int p = 0;
    for (int r = 0; r < TOPK; r++) {
        bool valid = (p < TOPK);
        sval[tid] = valid ? lv[p] : -INFINITY;
        sidx[tid] = valid ? li[p] : INT_MAX;
        stid[tid] = tid;
        __syncthreads();
        for (int off = 128; off > 0; off >>= 1) {
            if (tid < off) {
                float v2 = sval[tid + off]; int i2 = sidx[tid + off];
                float v1 = sval[tid];       int i1 = sidx[tid];
                if (v2 > v1 || (v2 == v1 && i2 < i1)) {
                    sval[tid] = v2; sidx[tid] = i2; stid[tid] = stid[tid + off];
                }
            }
            __syncthreads();
        }
        if (tid == 0) {
            g_pval[beam][part][r] = sval[0];
            g_pidx[beam][part][r] = sidx[0];
        }
        int winner = stid[0];
        __syncthreads();
        if (tid == winner) p++;
    }

    // ---------------- fan-in: elect last block ----------------
    __threadfence();            // release partial writes
    if (tid == 0) {
        unsigned int done = atomicAdd(&g_counter, 1u);
        s_last = (done == (unsigned)(BEAM * PARTS - 1));
    }
    __syncthreads();
    if (!s_last) return;
    __threadfence();            // acquire: see all partials

    // ---------------- Phase B: merge (warp w = beam w) ----------------
    __shared__ float s_cand[BEAM * TOPK];   // prob incl. prev - lse
    __shared__ int   s_cidx[BEAM * TOPK];
    __shared__ int   s_beam[BEAM];
    __shared__ int   s_tbi[BEAM];

    const int wid  = tid >> 5;
    const int lane = tid & 31;

    if (wid < BEAM) {
        const int b = wid;
        // lane = part
        float pm = g_pm[b][lane];
        float ps = g_ps[b][lane];
        float nm = pm;
#pragma unroll
        for (int off = 16; off > 0; off >>= 1)
            nm = fmaxf(nm, __shfl_xor_sync(0xFFFFFFFFu, nm, off));
        float sc = ps * expf(pm - nm);
#pragma unroll
        for (int off = 16; off > 0; off >>= 1)
            sc += __shfl_xor_sync(0xFFFFFFFFu, sc, off);
        float base = prev_prob[b] - (nm + logf(sc));

        float mv[TOPK];
        int   mi[TOPK];
#pragma unroll
        for (int i = 0; i < TOPK; i++) {
            mv[i] = g_pval[b][lane][i];
            mi[i] = g_pidx[b][lane][i];
        }

        for (int r = 0; r < TOPK; r++) {
            // per-lane best of 8 (value desc, idx asc)
            float bv = -INFINITY; int bidx = INT_MAX; int bslot = 0;
#pragma unroll
            for (int i = 0; i < TOPK; i++) {
                if (mv[i] > bv || (mv[i] == bv && mi[i] < bidx)) {
                    bv = mv[i]; bidx = mi[i]; bslot = i;
                }
            }
            unsigned long long key =
                ((unsigned long long)ford(bv) << 32) |
                (unsigned long long)(0xFFFFFFFFu - (unsigned int)bidx);
            unsigned long long mk = key;
#pragma unroll
            for (int off = 16; off > 0; off >>= 1) {
                unsigned long long o = __shfl_xor_sync(0xFFFFFFFFu, mk, off);
                if (o > mk) mk = o;
            }
            float wv  = funord((unsigned int)(mk >> 32));
            int   widx = (int)(0xFFFFFFFFu - (unsigned int)(mk & 0xFFFFFFFFu));
            if (lane == 0) {
                s_cand[b * TOPK + r] = wv + base;
                s_cidx[b * TOPK + r] = widx;
            }
            if (key == mk) mv[bslot] = -INFINITY;   // pop (unique idx -> one lane)
        }
    }
    __syncthreads();

    // ---------------- Phase C: final select (serial over 64) ----------------
    if (tid == 0) {
        bool used[BEAM * TOPK];
#pragma unroll
        for (int c = 0; c < BEAM * TOPK; c++) used[c] = false;

        unsigned long long packed = 0ull;
        for (int r = 0; r < BEAM; r++) {
            int best = -1; float bv = -INFINITY;
            for (int c = 0; c < BEAM * TOPK; c++) {
                if (!used[c] && s_cand[c] > bv) { bv = s_cand[c]; best = c; }
            }
            used[best] = true;
            int bi = best >> 3;
            int ti = s_cidx[best];
            s_beam[r] = bi;
            s_tbi[r]  = ti;
            packed |= ((unsigned long long)(unsigned)bi) << (8 * r);
            out[OFF_PROB + r] = bv;
            out[OFF_TBI + r]  = (float)ti;
        }
        g_beam_packed = packed;
        g_counter = 0;                 // reset for next graph replay
        out[OFF_MAX] = (float)s_tbi[0];
    }
    __syncthreads();

    for (int e = tid; e < BEAM * (HIST + 1); e += blockDim.x) {
        int bn = e / (HIST + 1);
        int c  = e - bn * (HIST + 1);
        float v = (c < HIST) ? (float)save_id[s_beam[bn] * HIST + c]
                             : (float)s_tbi[bn];
        out[OFF_SAVE + e] = v;
    }
}

// ---------------------------------------------------------------------------
// Gather: 1 GiB beam-permuted copy of kv_cache, float4, coalesced, streaming.
// ---------------------------------------------------------------------------
__global__ void __launch_bounds__(256) gather_kernel(const float4* __restrict__ kv,
                                                     float4*       __restrict__ out)
{
    unsigned int tid = blockIdx.x * 256u + threadIdx.x;
    const unsigned int stride = 4096u * 256u;   // 1,048,576

    unsigned long long packed = g_beam_packed;

#pragma unroll 8
    for (int it = 0; it < TOTAL4 / (4096 * 256); it++) {   // 64 iters
        unsigned int idx   = tid + (unsigned int)it * stride;
        unsigned int lb    = idx >> 18;                    // idx / CH4
        unsigned int inner = idx & (CH4 - 1u);
        unsigned int b     = lb & 7u;
        unsigned int l     = lb >> 3;
        unsigned int bm    = (unsigned int)((packed >> (8u * b)) & 0xFFull);
        unsigned int src   = ((l << 3) + bm) * (unsigned int)CH4 + inner;
        float4 v = kv[src];
        __stcs(&out[idx], v);
    }
}

// ---------------------------------------------------------------------------
extern "C" void kernel_launch(void* const* d_in, const int* in_sizes, int n_in,
                              void* d_out, int out_size)
{
    const float* kv_cache  = (const float*)d_in[0];
    const float* logits    = (const float*)d_in[1];
    const int*   save_id   = (const int*)d_in[2];
    const float* prev_prob = (const float*)d_in[3];
    float* out = (float*)d_out;

    selection_kernel<<<BEAM * PARTS, 256>>>(logits, prev_prob, save_id, out);
    gather_kernel<<<4096, 256>>>((const float4*)kv_cache, (float4*)out);
}

// round 6
// speedup vs baseline: 1.2928x; 1.1719x over previous
#include <cuda_runtime.h>
#include <math.h>
#include <limits.h>

// Problem constants
#define L_LAYERS 32
#define BEAM 8
#define KV2 2
#define HEADS 8
#define SEQ 1024
#define HDIM 64
#define VOCAB 50257
#define HIST 128
#define TOPK 8
#define PARTS 32
#define SEG ((VOCAB + PARTS - 1) / PARTS)   // 1571

// Derived
#define CH  (KV2*HEADS*SEQ*HDIM)        // floats per (layer, beam) chunk = 1,048,576
#define CH4 (CH/4)                      // float4 per chunk = 262,144
#define TOTAL4 (L_LAYERS*BEAM*CH4)      // 67,108,864 float4

#define SEL_BLOCKS (BEAM * PARTS)       // 256
#define GATHER_BLOCKS 4096
#define GRID (SEL_BLOCKS + GATHER_BLOCKS)
#define GITERS (TOTAL4 / (GATHER_BLOCKS * 256))   // 64

// Output layout (flattened tuple, all as float32)
#define OFF_SAVE 268435456
#define OFF_PROB (OFF_SAVE + BEAM*(HIST+1))
#define OFF_TBI  (OFF_PROB + BEAM)
#define OFF_MAX  (OFF_TBI + BEAM)

// Device scratch (no allocations allowed)
__device__ float g_pm[BEAM][PARTS];
__device__ float g_ps[BEAM][PARTS];
__device__ float g_pval[BEAM][PARTS][TOPK];
__device__ int   g_pidx[BEAM][PARTS][TOPK];
__device__ unsigned int g_counter = 0;   // selection fan-in
__device__ unsigned int g_ready   = 0;   // selection -> gather flag
__device__ unsigned int g_done    = 0;   // gather fan-in (reset flag)
__device__ unsigned long long g_dmask;   // bit (8*src + dest): dest d reads src s

// ordered-float mapping: monotonic float -> uint32
__device__ __forceinline__ unsigned int ford(float v) {
    unsigned int u = __float_as_uint(v);
    return (u & 0x80000000u) ? ~u : (u | 0x80000000u);
}
__device__ __forceinline__ float funord(unsigned int u) {
    u = (u & 0x80000000u) ? (u & 0x7FFFFFFFu) : ~u;
    return __uint_as_float(u);
}

// ---------------------------------------------------------------------------
// Single fused kernel.
//   blocks [0, 256):       selection (partials + fan-in merge + select)
//   blocks [256, 4352):    gather, spin-wait on g_ready, source-major dedup
// ---------------------------------------------------------------------------
__global__ void __launch_bounds__(256, 8)
fused_kernel(const float*  __restrict__ logits,
             const float*  __restrict__ prev_prob,
             const int*    __restrict__ save_id,
             const float4* __restrict__ kv,
             float*        __restrict__ out)
{
    const int tid = threadIdx.x;

    // ===================== GATHER PATH =====================
    if (blockIdx.x >= SEL_BLOCKS) {
        __shared__ unsigned long long sh_dmask;

        if (tid == 0) {
            // spin until selection publishes (release via threadfence+atomicExch)
            while (*(volatile unsigned int*)&g_ready == 0u) __nanosleep(64);
            __threadfence();                 // acquire
            sh_dmask = g_dmask;
        }
        __syncthreads();
        const unsigned long long dmask = sh_dmask;

        float4* __restrict__ kvout = (float4*)out;
        unsigned int gtid = (blockIdx.x - SEL_BLOCKS) * 256u + tid;
        const unsigned int stride = GATHER_BLOCKS * 256u;      // 1,048,576

#pragma unroll 4
        for (int it = 0; it < GITERS; it++) {
            unsigned int idx   = gtid + (unsigned int)it * stride; // = (l*8+s)*CH4+inner
            unsigned int lb    = idx >> 18;                        // l*8 + s
            unsigned int inner = idx & (CH4 - 1u);
            unsigned int msk   = (unsigned int)((dmask >> ((lb & 7u) * 8u)) & 0xFFull);
            if (msk) {
                float4 v = __ldcs(&kv[idx]);                       // linear read, once per live src
                unsigned int lbase = (lb & ~7u) * (unsigned int)CH4 + inner;
                do {
                    unsigned int d = (unsigned int)__ffs(msk) - 1u;
                    msk &= msk - 1u;
                    __stcs(&kvout[lbase + d * (unsigned int)CH4], v);
                } while (msk);
            }
        }

        // last gather block resets flags for next graph replay
        if (tid == 0) {
            unsigned int d = atomicAdd(&g_done, 1u);
            if (d == (unsigned)(GATHER_BLOCKS - 1)) {
                g_done  = 0u;
                g_ready = 0u;
            }
        }
        return;
    }

    // ===================== SELECTION PATH =====================
    const int blk  = blockIdx.x;
    const int beam = blk >> 5;        // / PARTS
    const int part = blk & 31;        // % PARTS
    const float* row = logits + beam * VOCAB;

    const int start = part * SEG;
    const int end   = min(start + SEG, VOCAB);

    __shared__ float sval[256];
    __shared__ float ssum[256];
    __shared__ int   sidx[256];
    __shared__ int   stid[256];
    __shared__ int   s_last;

    // ---------------- Phase A: partials ----------------
    float lv[TOPK];
    int   li[TOPK];
#pragma unroll
    for (int i = 0; i < TOPK; i++) { lv[i] = -INFINITY; li[i] = INT_MAX; }

    float m = -INFINITY, s = 0.0f;
    for (int j = start + tid; j < end; j += 256) {
        float v = row[j];
        if (v > m) { s = s * expf(m - v) + 1.0f; m = v; }
        else       { s += expf(v - m); }
        if (v > lv[TOPK - 1]) {
            int p = TOPK - 1;
#pragma unroll
            for (int q = TOPK - 1; q > 0; q--) {
                if (v > lv[q - 1]) { lv[q] = lv[q - 1]; li[q] = li[q - 1]; p = q - 1; }
            }
            lv[p] = v; li[p] = j;
        }
    }

    // block reduce (m, s)
    sval[tid] = m; ssum[tid] = s;
    __syncthreads();
    for (int off = 128; off > 0; off >>= 1) {
        if (tid < off) {
            float m2 = sval[tid + off], s2 = ssum[tid + off];
            float m1 = sval[tid],       s1 = ssum[tid];
            float nm = fmaxf(m1, m2);
            ssum[tid] = s1 * expf(m1 - nm) + s2 * expf(m2 - nm);
            sval[tid] = nm;
        }
        __syncthreads();
    }
    if (tid == 0) { g_pm[beam][part] = sval[0]; g_ps[beam][part] = ssum[0]; }
    __syncthreads();

    // 8 rounds of block argmax over each thread's sorted-list head
    int p = 0;
    for (int r = 0; r < TOPK; r++) {
        bool valid = (p < TOPK);
        sval[tid] = valid ? lv[p] : -INFINITY;
        sidx[tid] = valid ? li[p] : INT_MAX;
        stid[tid] = tid;
        __syncthreads();
        for (int off = 128; off > 0; off >>= 1) {
            if (tid < off) {
                float v2 = sval[tid + off]; int i2 = sidx[tid + off];
                float v1 = sval[tid];       int i1 = sidx[tid];
                if (v2 > v1 || (v2 == v1 && i2 < i1)) {
                    sval[tid] = v2; sidx[tid] = i2; stid[tid] = stid[tid + off];
                }
            }
            __syncthreads();
        }
        if (tid == 0) {
            g_pval[beam][part][r] = sval[0];
            g_pidx[beam][part][r] = sidx[0];
        }
        int winner = stid[0];
        __syncthreads();
        if (tid == winner) p++;
    }

    // ---------------- fan-in: elect last selection block ----------------
    __threadfence();            // release partial writes
    if (tid == 0) {
        unsigned int done = atomicAdd(&g_counter, 1u);
        s_last = (done == (unsigned)(SEL_BLOCKS - 1));
    }
    __syncthreads();
    if (!s_last) return;
    __threadfence();            // acquire: see all partials

    // ---------------- Phase B: merge (warp w = beam w) ----------------
    __shared__ float s_cand[BEAM * TOPK];
    __shared__ int   s_cidx[BEAM * TOPK];
    __shared__ int   s_beam[BEAM];
    __shared__ int   s_tbi[BEAM];

    const int wid  = tid >> 5;
    const int lane = tid & 31;

    if (wid < BEAM) {
        const int b = wid;
        float pm = g_pm[b][lane];
        float ps = g_ps[b][lane];
        float nm = pm;
#pragma unroll
        for (int off = 16; off > 0; off >>= 1)
            nm = fmaxf(nm, __shfl_xor_sync(0xFFFFFFFFu, nm, off));
        float sc = ps * expf(pm - nm);
#pragma unroll
        for (int off = 16; off > 0; off >>= 1)
            sc += __shfl_xor_sync(0xFFFFFFFFu, sc, off);
        float base = prev_prob[b] - (nm + logf(sc));

        float mv[TOPK];
        int   mi[TOPK];
#pragma unroll
        for (int i = 0; i < TOPK; i++) {
            mv[i] = g_pval[b][lane][i];
            mi[i] = g_pidx[b][lane][i];
        }

        for (int r = 0; r < TOPK; r++) {
            float bv = -INFINITY; int bidx = INT_MAX; int bslot = 0;
#pragma unroll
            for (int i = 0; i < TOPK; i++) {
                if (mv[i] > bv || (mv[i] == bv && mi[i] < bidx)) {
                    bv = mv[i]; bidx = mi[i]; bslot = i;
                }
            }
            unsigned long long key =
                ((unsigned long long)ford(bv) << 32) |
                (unsigned long long)(0xFFFFFFFFu - (unsigned int)bidx);
            unsigned long long mk = key;
#pragma unroll
            for (int off = 16; off > 0; off >>= 1) {
                unsigned long long o = __shfl_xor_sync(0xFFFFFFFFu, mk, off);
                if (o > mk) mk = o;
            }
            float wv   = funord((unsigned int)(mk >> 32));
            int   widx = (int)(0xFFFFFFFFu - (unsigned int)(mk & 0xFFFFFFFFu));
            if (lane == 0) {
                s_cand[b * TOPK + r] = wv + base;
                s_cidx[b * TOPK + r] = widx;
            }
            if (key == mk) mv[bslot] = -INFINITY;   // pop (unique idx -> one lane)
        }
    }
    __syncthreads();

    // ---------------- Phase C: final select + publish ----------------
    if (tid == 0) {
        bool used[BEAM * TOPK];
#pragma unroll
        for (int c = 0; c < BEAM * TOPK; c++) used[c] = false;

        unsigned long long dmask = 0ull;
        for (int r = 0; r < BEAM; r++) {
            int best = -1; float bv = -INFINITY;
            for (int c = 0; c < BEAM * TOPK; c++) {
                if (!used[c] && s_cand[c] > bv) { bv = s_cand[c]; best = c; }
            }
            used[best] = true;
            int bi = best >> 3;              // source beam
            int ti = s_cidx[best];
            s_beam[r] = bi;
            s_tbi[r]  = ti;
            dmask |= 1ull << (8 * bi + r);   // dest r reads source bi
            out[OFF_PROB + r] = bv;
            out[OFF_TBI + r]  = (float)ti;
        }
        out[OFF_MAX] = (float)s_tbi[0];
        g_dmask   = dmask;
        g_counter = 0;                       // reset fan-in for next replay
        __threadfence();                     // release dmask before flag
        atomicExch(&g_ready, 1u);            // wake gather blocks
    }
    __syncthreads();

    // new_save_id
    for (int e = tid; e < BEAM * (HIST + 1); e += blockDim.x) {
        int bn = e / (HIST + 1);
        int c  = e - bn * (HIST + 1);
        float v = (c < HIST) ? (float)save_id[s_beam[bn] * HIST + c]
                             : (float)s_tbi[bn];
        out[OFF_SAVE + e] = v;
    }
}

// ---------------------------------------------------------------------------
extern "C" void kernel_launch(void* const* d_in, const int* in_sizes, int n_in,
                              void* d_out, int out_size)
{
    const float* kv_cache  = (const float*)d_in[0];
    const float* logits    = (const float*)d_in[1];
    const int*   save_id   = (const int*)d_in[2];
    const float* prev_prob = (const float*)d_in[3];
    float* out = (float*)d_out;

    fused_kernel<<<GRID, 256>>>(logits, prev_prob, save_id,
                                (const float4*)kv_cache, out);
}

// round 8
// speedup vs baseline: 1.4108x; 1.0912x over previous
#include <cuda_runtime.h>
#include <math.h>
#include <limits.h>

// Problem constants
#define L_LAYERS 32
#define BEAM 8
#define KV2 2
#define HEADS 8
#define SEQ 1024
#define HDIM 64
#define VOCAB 50257
#define HIST 128
#define TOPK 8
#define PARTS 32
#define SEG ((VOCAB + PARTS - 1) / PARTS)   // 1571

// Derived
#define CH  (KV2*HEADS*SEQ*HDIM)        // floats per (layer, beam) chunk = 1,048,576
#define CH4 (CH/4)                      // float4 per chunk = 262,144
#define TOTAL4 (L_LAYERS*BEAM*CH4)      // 67,108,864 float4

#define SEL_BLOCKS (BEAM * PARTS)       // 256
#define GATHER_BLOCKS 4096
#define GRID (SEL_BLOCKS + GATHER_BLOCKS)
#define GSTRIDE (GATHER_BLOCKS * 256u)  // 1,048,576 threads
// L_LAYERS*CH4 = 8,388,608 = 8 * GSTRIDE  ->  iterations per thread = 8*d

// Output layout (flattened tuple, all as float32)
#define OFF_SAVE 268435456
#define OFF_PROB (OFF_SAVE + BEAM*(HIST+1))
#define OFF_TBI  (OFF_PROB + BEAM)
#define OFF_MAX  (OFF_TBI + BEAM)

// Device scratch (no allocations allowed)
__device__ float g_pm[BEAM][PARTS];
__device__ float g_ps[BEAM][PARTS];
__device__ float g_pval[BEAM][PARTS][TOPK];
__device__ int   g_pidx[BEAM][PARTS][TOPK];
__device__ unsigned int g_counter = 0;   // selection fan-in
__device__ unsigned int g_ready   = 0;   // selection -> gather flag
__device__ unsigned int g_done    = 0;   // gather fan-in (reset flag)
__device__ int          g_nsrc;          // number of distinct live sources
__device__ unsigned int g_work[BEAM];    // src(3b) | dest_mask<<8

// ordered-float mapping: monotonic float -> uint32
__device__ __forceinline__ unsigned int ford(float v) {
    unsigned int u = __float_as_uint(v);
    return (u & 0x80000000u) ? ~u : (u | 0x80000000u);
}
__device__ __forceinline__ float funord(unsigned int u) {
    u = (u & 0x80000000u) ? (u & 0x7FFFFFFFu) : ~u;
    return __uint_as_float(u);
}

// ---------------------------------------------------------------------------
// Single fused kernel.
//   blocks [0, 256):       selection (partials + fan-in merge + select)
//   blocks [256, 4352):    gather, spin-wait on g_ready, compact work list
// ---------------------------------------------------------------------------
__global__ void __launch_bounds__(256, 8)
fused_kernel(const float*  __restrict__ logits,
             const float*  __restrict__ prev_prob,
             const int*    __restrict__ save_id,
             const float4* __restrict__ kv,
             float*        __restrict__ out)
{
    const int tid = threadIdx.x;

    // ===================== GATHER PATH =====================
    if (blockIdx.x >= SEL_BLOCKS) {
        __shared__ unsigned int sh_work[BEAM];
        __shared__ int sh_d;

        if (tid == 0) {
            while (*(volatile unsigned int*)&g_ready == 0u) __nanosleep(64);
            __threadfence();                 // acquire
            sh_d = g_nsrc;
        }
        __syncthreads();
        if (tid < BEAM) sh_work[tid] = g_work[tid];
        __syncthreads();

        const unsigned int d = (unsigned int)sh_d;
        const int iters = 8 * (int)d;        // uniform across all threads

        float4* __restrict__ kvout = (float4*)out;
        const unsigned int gtid = (blockIdx.x - SEL_BLOCKS) * 256u + tid;

        // items: ((l*d + k)*CH4 + inner), total = 32*d*CH4 = iters*GSTRIDE
        for (int it = 0; it < iters; it++) {
            unsigned int idx   = gtid + (unsigned int)it * GSTRIDE;
            unsigned int ld    = idx >> 18;               // l*d + k
            unsigned int inner = idx & (CH4 - 1u);
            unsigned int l     = ld / d;
            unsigned int k     = ld - l * d;
            unsigned int w     = sh_work[k];
            unsigned int src   = w & 7u;
            unsigned int msk   = w >> 8;
            float4 v = __ldcs(&kv[(l * 8u + src) * (unsigned int)CH4 + inner]);
            unsigned int lbase = l * 8u * (unsigned int)CH4 + inner;
            do {
                unsigned int r = (unsigned int)__ffs(msk) - 1u;
                msk &= msk - 1u;
                __stcs(&kvout[lbase + r * (unsigned int)CH4], v);
            } while (msk);
        }

        // last gather block resets flags for next graph replay
        if (tid == 0) {
            unsigned int dn = atomicAdd(&g_done, 1u);
            if (dn == (unsigned)(GATHER_BLOCKS - 1)) {
                g_done  = 0u;
                g_ready = 0u;
            }
        }
        return;
    }

    // ===================== SELECTION PATH =====================
    const int blk  = blockIdx.x;
    const int beam = blk >> 5;        // / PARTS
    const int part = blk & 31;        // % PARTS
    const float* row = logits + beam * VOCAB;

    const int start = part * SEG;
    const int end   = min(start + SEG, VOCAB);

    __shared__ float sval[256];
    __shared__ float ssum[256];
    __shared__ int   sidx[256];
    __shared__ int   stid[256];
    __shared__ int   s_last;

    // ---------------- Phase A: partials ----------------
    float lv[TOPK];
    int   li[TOPK];
#pragma unroll
    for (int i = 0; i < TOPK; i++) { lv[i] = -INFINITY; li[i] = INT_MAX; }

    float m = -INFINITY, s = 0.0f;
    for (int j = start + tid; j < end; j += 256) {
        float v = row[j];
        if (v > m) { s = s * expf(m - v) + 1.0f; m = v; }
        else       { s += expf(v - m); }
        if (v > lv[TOPK - 1]) {
            int p = TOPK - 1;
#pragma unroll
            for (int q = TOPK - 1; q > 0; q--) {
                if (v > lv[q - 1]) { lv[q] = lv[q - 1]; li[q] = li[q - 1]; p = q - 1; }
            }
            lv[p] = v; li[p] = j;
        }
    }

    // block reduce (m, s)
    sval[tid] = m; ssum[tid] = s;
    __syncthreads();
    for (int off = 128; off > 0; off >>= 1) {
        if (tid < off) {
            float m2 = sval[tid + off], s2 = ssum[tid + off];
            float m1 = sval[tid],       s1 = ssum[tid];
            float nm = fmaxf(m1, m2);
            ssum[tid] = s1 * expf(m1 - nm) + s2 * expf(m2 - nm);
            sval[tid] = nm;
        }
        __syncthreads();
    }
    if (tid == 0) { g_pm[beam][part] = sval[0]; g_ps[beam][part] = ssum[0]; }
    __syncthreads();

    // 8 rounds of block argmax over each thread's sorted-list head
    int p = 0;
    for (int r = 0; r < TOPK; r++) {
        bool valid = (p < TOPK);
        sval[tid] = valid ? lv[p] : -INFINITY;
        sidx[tid] = valid ? li[p] : INT_MAX;
        stid[tid] = tid;
        __syncthreads();
        for (int off = 128; off > 0; off >>= 1) {
            if (tid < off) {
                float v2 = sval[tid + off]; int i2 = sidx[tid + off];
                float v1 = sval[tid];       int i1 = sidx[tid];
                if (v2 > v1 || (v2 == v1 && i2 < i1)) {
                    sval[tid] = v2; sidx[tid] = i2; stid[tid] = stid[tid + off];
                }
            }
            __syncthreads();
        }
        if (tid == 0) {
            g_pval[beam][part][r] = sval[0];
            g_pidx[beam][part][r] = sidx[0];
        }
        int winner = stid[0];
        __syncthreads();
        if (tid == winner) p++;
    }

    // ---------------- fan-in: elect last selection block ----------------
    __threadfence();            // release partial writes
    if (tid == 0) {
        unsigned int done = atomicAdd(&g_counter, 1u);
        s_last = (done == (unsigned)(SEL_BLOCKS - 1));
    }
    __syncthreads();
    if (!s_last) return;
    __threadfence();            // acquire: see all partials

    // ---------------- Phase B: merge (warp w = beam w) ----------------
    __shared__ float s_cand[BEAM * TOPK];
    __shared__ int   s_cidx[BEAM * TOPK];
    __shared__ int   s_beam[BEAM];
    __shared__ int   s_tbi[BEAM];

    const int wid  = tid >> 5;
    const int lane = tid & 31;

    if (wid < BEAM) {
        const int b = wid;
        float pm = g_pm[b][lane];
        float ps = g_ps[b][lane];
        float nm = pm;
#pragma unroll
        for (int off = 16; off > 0; off >>= 1)
            nm = fmaxf(nm, __shfl_xor_sync(0xFFFFFFFFu, nm, off));
        float sc = ps * expf(pm - nm);
#pragma unroll
        for (int off = 16; off > 0; off >>= 1)
            sc += __shfl_xor_sync(0xFFFFFFFFu, sc, off);
        float base = prev_prob[b] - (nm + logf(sc));

        float mv[TOPK];
        int   mi[TOPK];
#pragma unroll
        for (int i = 0; i < TOPK; i++) {
            mv[i] = g_pval[b][lane][i];
            mi[i] = g_pidx[b][lane][i];
        }

        for (int r = 0; r < TOPK; r++) {
            float bv = -INFINITY; int bidx = INT_MAX; int bslot = 0;
#pragma unroll
            for (int i = 0; i < TOPK; i++) {
                if (mv[i] > bv || (mv[i] == bv && mi[i] < bidx)) {
                    bv = mv[i]; bidx = mi[i]; bslot = i;
                }
            }
            unsigned long long key =
                ((unsigned long long)ford(bv) << 32) |
                (unsigned long long)(0xFFFFFFFFu - (unsigned int)bidx);
            unsigned long long mk = key;
#pragma unroll
            for (int off = 16; off > 0; off >>= 1) {
                unsigned long long o = __shfl_xor_sync(0xFFFFFFFFu, mk, off);
                if (o > mk) mk = o;
            }
            float wv   = funord((unsigned int)(mk >> 32));
            int   widx = (int)(0xFFFFFFFFu - (unsigned int)(mk & 0xFFFFFFFFu));
            if (lane == 0) {
                s_cand[b * TOPK + r] = wv + base;
                s_cidx[b * TOPK + r] = widx;
            }
            if (key == mk) mv[bslot] = -INFINITY;   // pop (unique idx -> one lane)
        }
    }
    __syncthreads();

    // ---------------- Phase C: final select + compact work list ----------------
    if (tid == 0) {
        bool used[BEAM * TOPK];
#pragma unroll
        for (int c = 0; c < BEAM * TOPK; c++) used[c] = false;

        int          srcs[BEAM];
        unsigned int masks[BEAM];
        int nsrc = 0;

        for (int r = 0; r < BEAM; r++) {
            int best = -1; float bv = -INFINITY;
            for (int c = 0; c < BEAM * TOPK; c++) {
                if (!used[c] && s_cand[c] > bv) { bv = s_cand[c]; best = c; }
            }
            used[best] = true;
            int bi = best >> 3;              // source beam
            int ti = s_cidx[best];
            s_beam[r] = bi;
            s_tbi[r]  = ti;

            int k;
            for (k = 0; k < nsrc; k++) if (srcs[k] == bi) break;
            if (k == nsrc) { srcs[nsrc] = bi; masks[nsrc] = 0u; nsrc++; }
            masks[k] |= 1u << r;

            out[OFF_PROB + r] = bv;
            out[OFF_TBI + r]  = (float)ti;
        }
        out[OFF_MAX] = (float)s_tbi[0];

        for (int k = 0; k < nsrc; k++)
            g_work[k] = (unsigned int)srcs[k] | (masks[k] << 8);
        g_nsrc    = nsrc;
        g_counter = 0;                       // reset fan-in for next replay
        __threadfence();                     // release work list before flag
        atomicExch(&g_ready, 1u);            // wake gather blocks
    }
    __syncthreads();

    // new_save_id
    for (int e = tid; e < BEAM * (HIST + 1); e += blockDim.x) {
        int bn = e / (HIST + 1);
        int c  = e - bn * (HIST + 1);
        float v = (c < HIST) ? (float)save_id[s_beam[bn] * HIST + c]
                             : (float)s_tbi[bn];
        out[OFF_SAVE + e] = v;
    }
}

// ---------------------------------------------------------------------------
extern "C" void kernel_launch(void* const* d_in, const int* in_sizes, int n_in,
                              void* d_out, int out_size)
{
    const float* kv_cache  = (const float*)d_in[0];
    const float* logits    = (const float*)d_in[1];
    const int*   save_id   = (const int*)d_in[2];
    const float* prev_prob = (const float*)d_in[3];
    float* out = (float*)d_out;

    fused_kernel<<<GRID, 256>>>(logits, prev_prob, save_id,
                                (const float4*)kv_cache, out);
}